// round 10
// baseline (speedup 1.0000x reference)
#include <cuda_runtime.h>
#include <cuda_bf16.h>

// ProbabilityAdjustedLoss: B=8388608 rows, logits [B,2] fp32, labels [B] int32.
// Streaming reduction: 100.7 MB in, 4 B out. The working set fits in L2
// (126 MB), and graph replays run warm: wall 14.85us < cold-cache ncu 19.9us.
// Wall BW = 6.8 TB/s ~= the LTS chip cap (~6300 B/cyc, path-independent) —
// this kernel sits at the binding hardware ceiling.
//
// Proven levers (kept):
//  - single resident wave: 1184 blocks x 256 threads (148 SMs x 8 CTAs)     [R6]
//  - 4 rows/iter, 3 front-batched LDG.128 (MLP_p1=3; 6 loads regressed)     [R5]
//  - division-free math: -log(p_sel) = log(1+exp(±(l1-l0))); MUFU rcp only
//    feeds the stop-gradient weight; bit-exact vs reference (rel_err 0.0)   [R4]
//  - DEFAULT-policy loads: __ldcs evict-first destroyed warm-L2 replays
//    (14.85 -> 21.2us, R9). Do not add streaming hints here.
//  - deterministic cross-block combine: Q32.32 fixed-point integer atomics,
//    last block writes mean + resets state for the next graph replay        [R3]

#define NBLOCKS 1184   // 148 SMs * 8 CTAs/SM = exactly one full wave
#define NTHREADS 256
#define FIXED_SCALE 4294967296.0  // 2^32

__device__ unsigned long long g_acc = 0ULL;
__device__ unsigned int g_ticket = 0u;

__device__ __forceinline__ float row_loss(float l0, float l1, int lab) {
    const bool stable = (lab == 0);
    const float d = l1 - l0;
    const float x = stable ? d : -d;         // x s.t. p_sel = 1/(1+exp(x))
    const float u = 1.0f + __expf(x);        // 1/p_sel
    const float p = __fdividef(1.0f, u);     // MUFU rcp, weight path only

    const float thresh = stable ? 0.95f : 0.05f;
    const float slope  = stable ? 10.0f : (1.0f / 0.95f);
    const float basev  = stable ? 1.0f  : 2.0f;
    const float floorv = stable ? 0.1f  : 0.5f;
    const float w = fmaxf(floorv, fmaf(-slope, fmaxf(0.0f, p - thresh), basev));

    return w * __logf(u);                    // = -w * log(p_sel)
}

__global__ void __launch_bounds__(NTHREADS, 8)
loss_fused_kernel(const float4* __restrict__ logits2,  // 2 rows per float4
                  const int4* __restrict__ labels4,    // 4 labels per int4
                  float* __restrict__ out,
                  int nquads, int qsplit, float inv_B) {
    float acc = 0.0f;
    const int stride = gridDim.x * blockDim.x;
    const int tid0 = blockIdx.x * blockDim.x + threadIdx.x;

    // Main range — default policy (stays warm in L2 across graph replays)
    for (int i = tid0; i < qsplit; i += stride) {
        const float4 lgA = logits2[2 * i + 0];
        const float4 lgB = logits2[2 * i + 1];
        const int4   lb  = labels4[i];
        acc += row_loss(lgA.x, lgA.y, lb.x);
        acc += row_loss(lgA.z, lgA.w, lb.y);
        acc += row_loss(lgB.x, lgB.y, lb.z);
        acc += row_loss(lgB.z, lgB.w, lb.w);
    }

    // Tail range — evict-first (25% of traffic; neutral vs default, keeps
    // the protected set untouched)
    for (int i = qsplit + tid0; i < nquads; i += stride) {
        const float4 lgA = __ldcs(&logits2[2 * i + 0]);
        const float4 lgB = __ldcs(&logits2[2 * i + 1]);
        const int4   lb  = __ldcs(&labels4[i]);
        acc += row_loss(lgA.x, lgA.y, lb.x);
        acc += row_loss(lgA.z, lgA.w, lb.y);
        acc += row_loss(lgB.x, lgB.y, lb.z);
        acc += row_loss(lgB.z, lgB.w, lb.w);
    }

    // Block reduction
    __shared__ float sdata[NTHREADS];
    sdata[threadIdx.x] = acc;
    __syncthreads();
    #pragma unroll
    for (int s = NTHREADS / 2; s > 32; s >>= 1) {
        if (threadIdx.x < s) sdata[threadIdx.x] += sdata[threadIdx.x + s];
        __syncthreads();
    }

    __shared__ bool s_is_last;
    if (threadIdx.x < 32) {
        float v = sdata[threadIdx.x] + sdata[threadIdx.x + 32];
        #pragma unroll
        for (int off = 16; off > 0; off >>= 1)
            v += __shfl_down_sync(0xFFFFFFFFu, v, off);

        if (threadIdx.x == 0) {
            // Deterministic cross-block combine (integer add is associative).
            long long q = llrint((double)v * FIXED_SCALE);
            atomicAdd(&g_acc, (unsigned long long)q);
            __threadfence();
            unsigned int t = atomicAdd(&g_ticket, 1u);
            s_is_last = (t == (unsigned int)(gridDim.x - 1));
        }
    }
    __syncthreads();

    // Last block writes the mean and resets state for the next graph replay.
    if (s_is_last && threadIdx.x == 0) {
        unsigned long long total = atomicAdd(&g_acc, 0ULL);  // coherent read
        out[0] = (float)(((double)(long long)total / FIXED_SCALE) * (double)inv_B);
        g_acc = 0ULL;
        g_ticket = 0u;
    }
}

extern "C" void kernel_launch(void* const* d_in, const int* in_sizes, int n_in,
                              void* d_out, int out_size) {
    const float4* logits2 = (const float4*)d_in[0];  // [B,2] fp32 -> B/2 float4
    const int4*   labels4 = (const int4*)d_in[1];    // [B] int32 -> B/4 int4
    const int B = in_sizes[1];                       // label element count
    const int nquads = B / 4;
    const int qsplit = (nquads / 4) * 3;             // 75% default / 25% stream

    loss_fused_kernel<<<NBLOCKS, NTHREADS>>>(logits2, labels4, (float*)d_out,
                                             nquads, qsplit, 1.0f / (float)B);
}

// round 11
// speedup vs baseline: 1.5609x; 1.5609x over previous
#include <cuda_runtime.h>
#include <cuda_bf16.h>

// ProbabilityAdjustedLoss: B=8388608 rows, logits [B,2] fp32, labels [B] int32.
// Streaming reduction: 100.7 MB in, 4 B out. Working set fits in 126 MB L2;
// graph replays run warm (best wall 14.85us < cold-cache ncu ~19.9us).
// Wall BW ~6.8 TB/s ~= the LTS chip cap — at the binding hardware ceiling.
//
// NOTE on measurement: R8 and R10 ran byte-identical code and measured
// 14.85us vs 23.8us wall (ncu stable at ~19.8us both) -> wall-clock timing
// has large environmental variance (DVFS / L2 state). This is the converged
// kernel; structural probes are resolved:
//  - single resident wave: 1184 x 256 (148 SMs x 8 CTAs)                [R6 WIN]
//  - 4 rows/iter, 3 front-batched LDG.128; 6 loads regressed (L1tex q)  [R4 FAIL]
//  - division-free math, bit-exact (rel_err 0.0)                        [R4/R5 WIN]
//  - DEFAULT-policy loads; __ldcs killed warm-L2 replays (+6us)         [R9 FAIL]
//  - deterministic Q32.32 integer-atomic fused epilogue                 [R3/R5 WIN]

#define NBLOCKS 1184   // 148 SMs * 8 CTAs/SM = exactly one full wave
#define NTHREADS 256
#define FIXED_SCALE 4294967296.0  // 2^32

__device__ unsigned long long g_acc = 0ULL;
__device__ unsigned int g_ticket = 0u;

__device__ __forceinline__ float row_loss(float l0, float l1, int lab) {
    const bool stable = (lab == 0);
    const float d = l1 - l0;
    const float x = stable ? d : -d;         // x s.t. p_sel = 1/(1+exp(x))
    const float u = 1.0f + __expf(x);        // 1/p_sel
    const float p = __fdividef(1.0f, u);     // MUFU rcp, weight path only

    // label-selected weight constants; branchless clamp-fma-clamp
    const float thresh = stable ? 0.95f : 0.05f;
    const float slope  = stable ? 10.0f : (1.0f / 0.95f);
    const float basev  = stable ? 1.0f  : 2.0f;
    const float floorv = stable ? 0.1f  : 0.5f;
    const float w = fmaxf(floorv, fmaf(-slope, fmaxf(0.0f, p - thresh), basev));

    return w * __logf(u);                    // = -w * log(p_sel)
}

__global__ void __launch_bounds__(NTHREADS, 8)
loss_fused_kernel(const float4* __restrict__ logits2,  // 2 rows per float4
                  const int4* __restrict__ labels4,    // 4 labels per int4
                  float* __restrict__ out,
                  int nquads, float inv_B) {           // groups of 4 rows
    float acc = 0.0f;
    const int stride = gridDim.x * blockDim.x;
    for (int i = blockIdx.x * blockDim.x + threadIdx.x; i < nquads; i += stride) {
        // 3 front-batched wide loads (MLP_p1 = 3), default cache policy
        const float4 lgA = logits2[2 * i + 0];
        const float4 lgB = logits2[2 * i + 1];
        const int4   lb  = labels4[i];
        acc += row_loss(lgA.x, lgA.y, lb.x);
        acc += row_loss(lgA.z, lgA.w, lb.y);
        acc += row_loss(lgB.x, lgB.y, lb.z);
        acc += row_loss(lgB.z, lgB.w, lb.w);
    }

    // Block reduction
    __shared__ float sdata[NTHREADS];
    sdata[threadIdx.x] = acc;
    __syncthreads();
    #pragma unroll
    for (int s = NTHREADS / 2; s > 32; s >>= 1) {
        if (threadIdx.x < s) sdata[threadIdx.x] += sdata[threadIdx.x + s];
        __syncthreads();
    }

    __shared__ bool s_is_last;
    if (threadIdx.x < 32) {
        float v = sdata[threadIdx.x] + sdata[threadIdx.x + 32];
        #pragma unroll
        for (int off = 16; off > 0; off >>= 1)
            v += __shfl_down_sync(0xFFFFFFFFu, v, off);

        if (threadIdx.x == 0) {
            // Deterministic cross-block combine (integer add is associative).
            long long q = llrint((double)v * FIXED_SCALE);
            atomicAdd(&g_acc, (unsigned long long)q);
            __threadfence();
            unsigned int t = atomicAdd(&g_ticket, 1u);
            s_is_last = (t == (unsigned int)(gridDim.x - 1));
        }
    }
    __syncthreads();

    // Last block writes the mean and resets state for the next graph replay.
    if (s_is_last && threadIdx.x == 0) {
        unsigned long long total = atomicAdd(&g_acc, 0ULL);  // coherent read
        out[0] = (float)(((double)(long long)total / FIXED_SCALE) * (double)inv_B);
        g_acc = 0ULL;
        g_ticket = 0u;
    }
}

extern "C" void kernel_launch(void* const* d_in, const int* in_sizes, int n_in,
                              void* d_out, int out_size) {
    const float4* logits2 = (const float4*)d_in[0];  // [B,2] fp32 -> B/2 float4
    const int4*   labels4 = (const int4*)d_in[1];    // [B] int32 -> B/4 int4
    const int B = in_sizes[1];                       // label element count
    const int nquads = B / 4;

    loss_fused_kernel<<<NBLOCKS, NTHREADS>>>(logits2, labels4, (float*)d_out,
                                             nquads, 1.0f / (float)B);
}